// round 16
// baseline (speedup 1.0000x reference)
#include <cuda_runtime.h>
#include <cuda_fp16.h>
#include <math.h>

#define N_NODES 100000
#define N_EDGES 3200000
#define SCAN_BLOCK 1024
#define SCAN_NBLK ((N_NODES + SCAN_BLOCK - 1) / SCAN_BLOCK)   // 98 <= 148 SMs
#define SRC_MASK 0x1FFFF
#define Q15_INV (1.0f / 32767.0f)

// Device-global scratch (zero-init at load; g_deg/g_acc/g_sflag re-zeroed each run).
__device__ float4 g_x0[(size_t)N_NODES * 2];   // level-0 features fp32
__device__ float4 g_x1[(size_t)N_NODES * 2];   // level-1 features fp32 (for epi2)
__device__ uint4  g_yh[(size_t)N_NODES];       // conv1 operand fp16: dinv*(bv1+wv1*x0) 16B
__device__ uint4  g_r2h[(size_t)N_NODES * 2];  // conv2 operand fp16 {x1,d01} 32B
__device__ uint4  g_r3h[(size_t)N_NODES * 4];  // conv3 operand fp16 {x2,d02,d12,pad} 64B
__device__ float4 g_acc[(size_t)N_NODES * 2];  // per-layer accumulator
__device__ float4 g_q[(size_t)N_NODES * 2];    // per-node qk[8] (0.5*q*wk)
__device__ float  g_dinv[N_NODES];
__device__ int    g_deg[N_NODES];
__device__ int    g_cursor[N_NODES];
__device__ int2   g_csr[N_EDGES];     // {src | q15(dinv[src])<<17, dst} (no self loops)
__device__ int    g_bsum[SCAN_NBLK];
__device__ int    g_sflag;            // scan barrier; reset by fill_edges

// ---- fp16 pack/unpack (8 floats <-> uint4 of 8 halves) ----
__device__ __forceinline__ void h8_to_f(const uint4& u, float o[8]) {
    const __half2* h = (const __half2*)&u;
    #pragma unroll
    for (int i = 0; i < 4; i++) {
        float2 f = __half22float2(h[i]);
        o[2 * i] = f.x; o[2 * i + 1] = f.y;
    }
}
__device__ __forceinline__ uint4 f_to_h8(const float o[8]) {
    uint4 u;
    __half2* h = (__half2*)&u;
    #pragma unroll
    for (int i = 0; i < 4; i++)
        h[i] = __float22half2_rn(make_float2(o[2 * i], o[2 * i + 1]));
    return u;
}

// ---- packed f32x2 helpers ----
__device__ __forceinline__ unsigned long long ADDX2(unsigned long long a, unsigned long long b) {
    unsigned long long r;
    asm("add.rn.f32x2 %0, %1, %2;" : "=l"(r) : "l"(a), "l"(b));
    return r;
}
__device__ __forceinline__ unsigned long long PACK2(float lo, float hi) {
    unsigned long long r;
    asm("mov.b64 %0, {%1, %2};" : "=l"(r) : "f"(lo), "f"(hi));
    return r;
}
__device__ __forceinline__ void UNPACK2(unsigned long long v, float& lo, float& hi) {
    asm("mov.b64 {%0, %1}, %2;" : "=f"(lo), "=f"(hi) : "l"(v));
}
__device__ __forceinline__ void flush8(int dst, const float r[8]) {
    float* a = (float*)g_acc + (size_t)dst * 8;
    asm volatile("red.global.add.v4.f32 [%0], {%1,%2,%3,%4};"
                 :: "l"(a), "f"(r[0]), "f"(r[1]), "f"(r[2]), "f"(r[3]) : "memory");
    asm volatile("red.global.add.v4.f32 [%0], {%1,%2,%3,%4};"
                 :: "l"(a + 4), "f"(r[4]), "f"(r[5]), "f"(r[6]), "f"(r[7]) : "memory");
}
__device__ __forceinline__ unsigned lanemask_le() {
    unsigned m; asm("mov.u32 %0, %%lanemask_le;" : "=r"(m)); return m;
}

// paired (2 consecutive slots/lane) segmented reduction keyed by dst (-1 invalid)
__device__ __forceinline__ void pair_reduce_flush(
    const float mA[8], const float mB[8], int dstA, int dstB, int lane)
{
    int prevB = __shfl_up_sync(0xffffffffu, dstB, 1);
    bool start = (lane == 0) || (dstA != dstB) || (prevB != dstA);
    unsigned startmask = __ballot_sync(0xffffffffu, start);
    int segid = __popc(startmask & lanemask_le());

    if (dstA != dstB && dstA >= 0) flush8(dstA, mA);   // mid-lane segment close

    unsigned long long p[4];
    bool same = (dstA == dstB);
    #pragma unroll
    for (int i = 0; i < 4; i++) {
        unsigned long long b_ = PACK2(mB[2 * i], mB[2 * i + 1]);
        p[i] = same ? ADDX2(PACK2(mA[2 * i], mA[2 * i + 1]), b_) : b_;
    }
    #pragma unroll
    for (int off = 1; off < 32; off <<= 1) {
        int s2 = __shfl_up_sync(0xffffffffu, segid, off);
        bool take = (lane >= off) && (s2 == segid);
        #pragma unroll
        for (int i = 0; i < 4; i++) {
            unsigned long long t = __shfl_up_sync(0xffffffffu, p[i], off);
            if (take) p[i] = ADDX2(p[i], t);
        }
    }
    bool end = (lane == 31) || ((startmask >> (lane + 1)) & 1u);
    if (end && dstB >= 0) {
        float r[8];
        UNPACK2(p[0], r[0], r[1]); UNPACK2(p[1], r[2], r[3]);
        UNPACK2(p[2], r[4], r[5]); UNPACK2(p[3], r[6], r[7]);
        flush8(dstB, r);
    }
}

// ---------------- CSR build ----------------

__global__ void count_kernel(const int4* __restrict__ dst4) {
    int e = blockIdx.x * blockDim.x + threadIdx.x;
    if (e < N_EDGES / 4) {
        int4 d = __ldg(&dst4[e]);
        atomicAdd(&g_deg[d.x], 1);
        atomicAdd(&g_deg[d.y], 1);
        atomicAdd(&g_deg[d.z], 1);
        atomicAdd(&g_deg[d.w], 1);
    }
}

// fused scan: deg->dinv + block scan + co-resident barrier + global prefix +
// cursor init + input MLP + y record. All 98 blocks resident (<=148 SMs).
__global__ void __launch_bounds__(SCAN_BLOCK) scan_mlp_kernel(
    const float* __restrict__ x,
    const int* __restrict__ node_index,
    const float* __restrict__ emb,
    const float* __restrict__ W1,
    const float* __restrict__ b1,
    const float* __restrict__ Wv1,
    const float* __restrict__ Bv1)
{
    __shared__ float sW[24 * 8 + 8];
    __shared__ int wsum[32];
    __shared__ int sPre;
    int t = threadIdx.x, lane = t & 31, wid = t >> 5;
    if (t < 192) sW[t] = W1[t];
    else if (t < 200) sW[t] = b1[t - 192];

    int i = blockIdx.x * SCAN_BLOCK + t;
    int v = 0;
    float di = 0.0f;
    if (i < N_NODES) {
        v = g_deg[i];                      // edge in-degree (no self slot in CSR)
        di = rsqrtf((float)(v + 1));       // dinv includes self loop
        g_dinv[i] = di;
        g_deg[i] = 0;                      // restore entry invariant
    }
    int xs = v;
    #pragma unroll
    for (int o = 1; o < 32; o <<= 1) {
        int y = __shfl_up_sync(0xffffffffu, xs, o);
        if (lane >= o) xs += y;
    }
    if (lane == 31) wsum[wid] = xs;
    __syncthreads();
    if (wid == 0) {
        int s = wsum[lane];
        #pragma unroll
        for (int o = 1; o < 32; o <<= 1) {
            int y = __shfl_up_sync(0xffffffffu, s, o);
            if (lane >= o) s += y;
        }
        wsum[lane] = s;
    }
    __syncthreads();
    int incl = xs + (wid ? wsum[wid - 1] : 0);
    if (t == SCAN_BLOCK - 1) g_bsum[blockIdx.x] = incl;

    // co-resident barrier: all blocks' bsum visible before prefix read
    __threadfence();
    if (t == 0) {
        atomicAdd(&g_sflag, 1);
        while (*(volatile int*)&g_sflag < SCAN_NBLK) __nanosleep(64);
    }
    __syncthreads();
    __threadfence();

    if (t < 32) {                       // warp 0: prefix of bsum[0..bid)
        int s = 0;
        for (int j = t; j < SCAN_NBLK; j += 32)
            if (j < (int)blockIdx.x) s += g_bsum[j];
        #pragma unroll
        for (int o = 16; o; o >>= 1) s += __shfl_xor_sync(0xffffffffu, s, o);
        if (t == 0) sPre = s;
    }
    __syncthreads();
    if (i >= N_NODES) return;

    g_cursor[i] = (incl - v) + sPre;    // exclusive edge offset

    float in[24];
    int idx = node_index[i];
    #pragma unroll
    for (int j = 0; j < 8; j++) in[j] = emb[(size_t)idx * 8 + j];
    #pragma unroll
    for (int j = 0; j < 16; j++) in[8 + j] = x[(size_t)i * 16 + j];
    float o[8], y[8];
    #pragma unroll
    for (int c = 0; c < 8; c++) {
        float s = sW[192 + c];
        #pragma unroll
        for (int j = 0; j < 24; j++) s = fmaf(in[j], sW[j * 8 + c], s);
        o[c] = fmaxf(s, 0.0f);
        y[c] = di * fmaf(__ldg(Wv1 + c), o[c], __ldg(Bv1 + c));
    }
    g_x0[(size_t)i * 2]     = make_float4(o[0], o[1], o[2], o[3]);
    g_x0[(size_t)i * 2 + 1] = make_float4(o[4], o[5], o[6], o[7]);
    g_yh[i] = f_to_h8(y);
}

__global__ void fill_edges_kernel(const int* __restrict__ src, const int* __restrict__ dst) {
    if (blockIdx.x == 0 && threadIdx.x == 0) g_sflag = 0;   // reset scan barrier
    int e = blockIdx.x * blockDim.x + threadIdx.x;
    if (e < N_EDGES) {
        int s = src[e];
        int d = dst[e];
        int q = __float2int_rn(g_dinv[s] * 32767.0f);
        int p = atomicAdd(&g_cursor[d], 1);
        g_csr[p] = make_int2(s | (q << 17), d);
    }
}

// ---------------- conv1: direct-gather SpMV of fp16 y ----------------------

__global__ void __launch_bounds__(256) econv1_kernel() {
    int warp = threadIdx.x >> 5, lane = threadIdx.x & 31;
    int base = (blockIdx.x * 8 + warp) * 64;
    if (base >= N_EDGES) return;
    int cnt = min(64, N_EDGES - base);

    int2 eA = make_int2(0, -1), eB = make_int2(0, -1);
    if (2 * lane + 1 < cnt) {
        int4 v = __ldg((const int4*)(g_csr + base + 2 * lane));
        eA = make_int2(v.x, v.y);
        eB = make_int2(v.z, v.w);
    } else if (2 * lane < cnt) {
        eA = __ldg(&g_csr[base + 2 * lane]);
    }

    float mA[8] = {0,0,0,0,0,0,0,0}, mB[8] = {0,0,0,0,0,0,0,0};
    if (eA.y >= 0) {
        uint4 ya = __ldg(&g_yh[eA.x & SRC_MASK]);
        h8_to_f(ya, mA);
    }
    if (eB.y >= 0) {
        uint4 yb = __ldg(&g_yh[eB.x & SRC_MASK]);
        h8_to_f(yb, mB);
    }
    pair_reduce_flush(mA, mB, eA.y, eB.y, lane);
}

// ---------------- conv2: direct-gather, fp16 records (32B/edge) ------------

__device__ __forceinline__ void conv2_msg(const uint4& c0, const uint4& c1,
                                          const float4& q0, const float4& q1,
                                          float w, const float* Wv, const float* Bv, float m[8]) {
    float x1[8], d01[8];
    h8_to_f(c0, x1);
    h8_to_f(c1, d01);
    float qk[8] = {q0.x, q0.y, q0.z, q0.w, q1.x, q1.y, q1.z, q1.w};
    float a[2];
    #pragma unroll
    for (int h = 0; h < 2; h++) {
        float s_ = 0.0f;
        #pragma unroll
        for (int d = 0; d < 4; d++) s_ = fmaf(qk[h * 4 + d], d01[h * 4 + d], s_);
        a[h] = 1.0f / (1.0f + __expf(-s_));
    }
    #pragma unroll
    for (int c = 0; c < 8; c++) {
        float t = fmaf(a[c >> 2], d01[c], x1[c]);
        m[c] = w * fmaf(__ldg(Wv + c), t, __ldg(Bv + c));
    }
}

__global__ void __launch_bounds__(256) econv2_kernel(
    const float* __restrict__ Wv, const float* __restrict__ Bv)
{
    int warp = threadIdx.x >> 5, lane = threadIdx.x & 31;
    int base = (blockIdx.x * 8 + warp) * 64;
    if (base >= N_EDGES) return;
    int cnt = min(64, N_EDGES - base);

    int2 eA = make_int2(0, -1), eB = make_int2(0, -1);
    if (2 * lane + 1 < cnt) {
        int4 v = __ldg((const int4*)(g_csr + base + 2 * lane));
        eA = make_int2(v.x, v.y);
        eB = make_int2(v.z, v.w);
    } else if (2 * lane < cnt) {
        eA = __ldg(&g_csr[base + 2 * lane]);
    }

    float mA[8] = {0,0,0,0,0,0,0,0}, mB[8] = {0,0,0,0,0,0,0,0};
    if (eA.y >= 0) {
        int s = eA.x & SRC_MASK;
        uint4 c0 = __ldg(g_r2h + (size_t)s * 2);
        uint4 c1 = __ldg(g_r2h + (size_t)s * 2 + 1);   // same 32B sector: L1 hit
        float4 q0 = __ldg(g_q + (size_t)eA.y * 2);
        float4 q1 = __ldg(g_q + (size_t)eA.y * 2 + 1);
        float w = (float)((unsigned)eA.x >> 17) * Q15_INV;
        conv2_msg(c0, c1, q0, q1, w, Wv, Bv, mA);
    }
    if (eB.y >= 0) {
        int s = eB.x & SRC_MASK;
        uint4 c0 = __ldg(g_r2h + (size_t)s * 2);
        uint4 c1 = __ldg(g_r2h + (size_t)s * 2 + 1);
        float4 q0 = __ldg(g_q + (size_t)eB.y * 2);
        float4 q1 = __ldg(g_q + (size_t)eB.y * 2 + 1);
        float w = (float)((unsigned)eB.x >> 17) * Q15_INV;
        conv2_msg(c0, c1, q0, q1, w, Wv, Bv, mB);
    }
    pair_reduce_flush(mA, mB, eA.y, eB.y, lane);
}

// ---------------- conv3: direct-gather, fp16 records (48B in 64B slot) -----

__device__ __forceinline__ void conv3_msg(const uint4& c0, const uint4& c1, const uint4& c2,
                                          const float4& q0, const float4& q1,
                                          float w, const float* Wv, const float* Bv, float m[8]) {
    float x2[8], d02[8], d12[8];
    h8_to_f(c0, x2);
    h8_to_f(c1, d02);
    h8_to_f(c2, d12);
    float qk[8] = {q0.x, q0.y, q0.z, q0.w, q1.x, q1.y, q1.z, q1.w};
    float a0[2], a1[2];
    #pragma unroll
    for (int h = 0; h < 2; h++) {
        float t0 = 0.0f, t1 = 0.0f;
        #pragma unroll
        for (int d = 0; d < 4; d++) {
            t0 = fmaf(qk[h * 4 + d], d02[h * 4 + d], t0);
            t1 = fmaf(qk[h * 4 + d], d12[h * 4 + d], t1);
        }
        float mx = fmaxf(fmaxf(t0, t1), 0.0f);
        float e0 = __expf(t0 - mx), e1 = __expf(t1 - mx), e2 = __expf(-mx);
        float inv = 1.0f / (e0 + e1 + e2);
        a0[h] = e0 * inv; a1[h] = e1 * inv;
    }
    #pragma unroll
    for (int c = 0; c < 8; c++) {
        int h = c >> 2;
        float t = fmaf(a0[h], d02[c], fmaf(a1[h], d12[c], x2[c]));
        m[c] = w * fmaf(__ldg(Wv + c), t, __ldg(Bv + c));
    }
}

__global__ void __launch_bounds__(256) econv3_kernel(
    const float* __restrict__ Wv, const float* __restrict__ Bv)
{
    int warp = threadIdx.x >> 5, lane = threadIdx.x & 31;
    int base = (blockIdx.x * 8 + warp) * 64;
    if (base >= N_EDGES) return;
    int cnt = min(64, N_EDGES - base);

    int2 eA = make_int2(0, -1), eB = make_int2(0, -1);
    if (2 * lane + 1 < cnt) {
        int4 v = __ldg((const int4*)(g_csr + base + 2 * lane));
        eA = make_int2(v.x, v.y);
        eB = make_int2(v.z, v.w);
    } else if (2 * lane < cnt) {
        eA = __ldg(&g_csr[base + 2 * lane]);
    }

    float mA[8] = {0,0,0,0,0,0,0,0}, mB[8] = {0,0,0,0,0,0,0,0};
    if (eA.y >= 0) {
        int s = eA.x & SRC_MASK;
        uint4 c0 = __ldg(g_r3h + (size_t)s * 4);
        uint4 c1 = __ldg(g_r3h + (size_t)s * 4 + 1);   // same 128B line: L1 hit
        uint4 c2 = __ldg(g_r3h + (size_t)s * 4 + 2);
        float4 q0 = __ldg(g_q + (size_t)eA.y * 2);
        float4 q1 = __ldg(g_q + (size_t)eA.y * 2 + 1);
        float w = (float)((unsigned)eA.x >> 17) * Q15_INV;
        conv3_msg(c0, c1, c2, q0, q1, w, Wv, Bv, mA);
    }
    if (eB.y >= 0) {
        int s = eB.x & SRC_MASK;
        uint4 c0 = __ldg(g_r3h + (size_t)s * 4);
        uint4 c1 = __ldg(g_r3h + (size_t)s * 4 + 1);
        uint4 c2 = __ldg(g_r3h + (size_t)s * 4 + 2);
        float4 q0 = __ldg(g_q + (size_t)eB.y * 2);
        float4 q1 = __ldg(g_q + (size_t)eB.y * 2 + 1);
        float w = (float)((unsigned)eB.x >> 17) * Q15_INV;
        conv3_msg(c0, c1, c2, q0, q1, w, Wv, Bv, mB);
    }
    pair_reduce_flush(mA, mB, eA.y, eB.y, lane);
}

// ---------------- epilogues (self-loop message added here) ----------------

__global__ void epi1_kernel(const float* __restrict__ Wq2, const float* __restrict__ Bq2,
                            const float* __restrict__ Wk2) {
    int n = blockIdx.x * blockDim.x + threadIdx.x;
    if (n >= N_NODES) return;
    float4 a = g_acc[(size_t)n * 2];
    float4 b = g_acc[(size_t)n * 2 + 1];
    float4 z4 = make_float4(0.f, 0.f, 0.f, 0.f);
    g_acc[(size_t)n * 2] = z4;
    g_acc[(size_t)n * 2 + 1] = z4;
    float acc[8] = {a.x, a.y, a.z, a.w, b.x, b.y, b.z, b.w};
    // self-loop message: y[n] (already dinv[n]-scaled)
    float ys[8];
    h8_to_f(g_yh[n], ys);
    #pragma unroll
    for (int c = 0; c < 8; c++) acc[c] += ys[c];
    float di = g_dinv[n];
    float x1[8];
    #pragma unroll
    for (int c = 0; c < 8; c++) x1[c] = fmaxf(di * acc[c], 0.f);
    float4 xa = g_x0[(size_t)n * 2];
    float4 xb = g_x0[(size_t)n * 2 + 1];
    float x0[8] = {xa.x, xa.y, xa.z, xa.w, xb.x, xb.y, xb.z, xb.w};
    float d01[8];
    #pragma unroll
    for (int c = 0; c < 8; c++) d01[c] = x0[c] - x1[c];
    g_x1[(size_t)n * 2]     = make_float4(x1[0], x1[1], x1[2], x1[3]);
    g_x1[(size_t)n * 2 + 1] = make_float4(x1[4], x1[5], x1[6], x1[7]);
    g_r2h[(size_t)n * 2]     = f_to_h8(x1);
    g_r2h[(size_t)n * 2 + 1] = f_to_h8(d01);
    float qk[8];
    #pragma unroll
    for (int c = 0; c < 8; c++) {
        float q = fmaf(x1[c], __ldg(Wq2 + c), __ldg(Bq2 + c));
        qk[c] = 0.5f * q * __ldg(Wk2 + c);
    }
    g_q[(size_t)n * 2]     = make_float4(qk[0], qk[1], qk[2], qk[3]);
    g_q[(size_t)n * 2 + 1] = make_float4(qk[4], qk[5], qk[6], qk[7]);
}

__global__ void epi2_kernel(const float* __restrict__ Wq3, const float* __restrict__ Bq3,
                            const float* __restrict__ Wk3,
                            const float* __restrict__ Wv2, const float* __restrict__ Bv2) {
    int n = blockIdx.x * blockDim.x + threadIdx.x;
    if (n >= N_NODES) return;
    float4 a = g_acc[(size_t)n * 2];
    float4 b = g_acc[(size_t)n * 2 + 1];
    float4 z4 = make_float4(0.f, 0.f, 0.f, 0.f);
    g_acc[(size_t)n * 2] = z4;
    g_acc[(size_t)n * 2 + 1] = z4;
    float acc[8] = {a.x, a.y, a.z, a.w, b.x, b.y, b.z, b.w};
    float di = g_dinv[n];
    // self-loop message (w = dinv[n]; dst factor applied below)
    {
        uint4 c0 = g_r2h[(size_t)n * 2];
        uint4 c1 = g_r2h[(size_t)n * 2 + 1];
        float4 q0 = g_q[(size_t)n * 2];
        float4 q1 = g_q[(size_t)n * 2 + 1];
        float ms[8];
        conv2_msg(c0, c1, q0, q1, di, Wv2, Bv2, ms);
        #pragma unroll
        for (int c = 0; c < 8; c++) acc[c] += ms[c];
    }
    float x2[8];
    #pragma unroll
    for (int c = 0; c < 8; c++) x2[c] = fmaxf(di * acc[c], 0.f);
    float4 xa = g_x0[(size_t)n * 2];
    float4 xb = g_x0[(size_t)n * 2 + 1];
    float4 ya = g_x1[(size_t)n * 2];
    float4 yb = g_x1[(size_t)n * 2 + 1];
    float x0[8] = {xa.x, xa.y, xa.z, xa.w, xb.x, xb.y, xb.z, xb.w};
    float x1[8] = {ya.x, ya.y, ya.z, ya.w, yb.x, yb.y, yb.z, yb.w};
    float d02[8], d12[8];
    #pragma unroll
    for (int c = 0; c < 8; c++) { d02[c] = x0[c] - x2[c]; d12[c] = x1[c] - x2[c]; }
    g_r3h[(size_t)n * 4]     = f_to_h8(x2);
    g_r3h[(size_t)n * 4 + 1] = f_to_h8(d02);
    g_r3h[(size_t)n * 4 + 2] = f_to_h8(d12);
    float qk[8];
    #pragma unroll
    for (int c = 0; c < 8; c++) {
        float q = fmaf(x2[c], __ldg(Wq3 + c), __ldg(Bq3 + c));
        qk[c] = 0.5f * q * __ldg(Wk3 + c);
    }
    g_q[(size_t)n * 2]     = make_float4(qk[0], qk[1], qk[2], qk[3]);
    g_q[(size_t)n * 2 + 1] = make_float4(qk[4], qk[5], qk[6], qk[7]);
}

__global__ void epi3_kernel(const float* __restrict__ W2, const float* __restrict__ b2,
                            const float* __restrict__ Wv3, const float* __restrict__ Bv3,
                            float* __restrict__ out) {
    int n = blockIdx.x * blockDim.x + threadIdx.x;
    if (n >= N_NODES) return;
    float4 a = g_acc[(size_t)n * 2];
    float4 b = g_acc[(size_t)n * 2 + 1];
    float4 z4 = make_float4(0.f, 0.f, 0.f, 0.f);
    g_acc[(size_t)n * 2] = z4;
    g_acc[(size_t)n * 2 + 1] = z4;
    float acc[8] = {a.x, a.y, a.z, a.w, b.x, b.y, b.z, b.w};
    float di = g_dinv[n];
    // self-loop message
    {
        uint4 c0 = g_r3h[(size_t)n * 4];
        uint4 c1 = g_r3h[(size_t)n * 4 + 1];
        uint4 c2 = g_r3h[(size_t)n * 4 + 2];
        float4 q0 = g_q[(size_t)n * 2];
        float4 q1 = g_q[(size_t)n * 2 + 1];
        float ms[8];
        conv3_msg(c0, c1, c2, q0, q1, di, Wv3, Bv3, ms);
        #pragma unroll
        for (int c = 0; c < 8; c++) acc[c] += ms[c];
    }
    float xl[8];
    #pragma unroll
    for (int c = 0; c < 8; c++) xl[c] = fmaxf(di * acc[c], 0.f);
    float z0 = __ldg(b2 + 0), z1 = __ldg(b2 + 1);
    #pragma unroll
    for (int c = 0; c < 8; c++) {
        z0 = fmaf(xl[c], __ldg(W2 + c * 2 + 0), z0);
        z1 = fmaf(xl[c], __ldg(W2 + c * 2 + 1), z1);
    }
    float mx = fmaxf(z0, z1);
    float lse = mx + __logf(__expf(z0 - mx) + __expf(z1 - mx));
    out[(size_t)n * 2 + 0] = z0 - lse;
    out[(size_t)n * 2 + 1] = z1 - lse;
}

// ---------------- launch ----------------

extern "C" void kernel_launch(void* const* d_in, const int* in_sizes, int n_in,
                              void* d_out, int out_size) {
    const float* x    = (const float*)d_in[0];
    const int*   nidx = (const int*)  d_in[1];
    const int*   eidx = (const int*)  d_in[3];   // [2, E]
    const float* emb  = (const float*)d_in[5];
    const float* W1   = (const float*)d_in[6];
    const float* b1   = (const float*)d_in[7];
    const float* Wq   = (const float*)d_in[8];
    const float* bq   = (const float*)d_in[9];
    const float* Wk   = (const float*)d_in[10];
    const float* Wv   = (const float*)d_in[12];
    const float* bv   = (const float*)d_in[13];
    const float* W2   = (const float*)d_in[14];
    const float* b2   = (const float*)d_in[15];
    float* out = (float*)d_out;

    const int* src = eidx;
    const int* dst = eidx + N_EDGES;

    int nb_n  = (N_NODES + 255) / 256;
    int nb_e  = (N_EDGES + 255) / 256;
    int nb_e4 = (N_EDGES / 4 + 255) / 256;
    int nb_p  = (N_EDGES + 511) / 512;            // 8 warps x 64 slots

    count_kernel<<<nb_e4, 256>>>((const int4*)dst);
    scan_mlp_kernel<<<SCAN_NBLK, SCAN_BLOCK>>>(x, nidx, emb, W1, b1, Wv + 0, bv + 0);
    fill_edges_kernel<<<nb_e, 256>>>(src, dst);

    econv1_kernel<<<nb_p, 256>>>();
    epi1_kernel<<<nb_n, 256>>>(Wq + 8, bq + 8, Wk + 8);
    econv2_kernel<<<nb_p, 256>>>(Wv + 8, bv + 8);
    epi2_kernel<<<nb_n, 256>>>(Wq + 16, bq + 16, Wk + 16, Wv + 8, bv + 8);
    econv3_kernel<<<nb_p, 256>>>(Wv + 16, bv + 16);
    epi3_kernel<<<nb_n, 256>>>(W2, b2, Wv + 16, bv + 16, out);
}

// round 17
// speedup vs baseline: 1.0691x; 1.0691x over previous
#include <cuda_runtime.h>
#include <cuda_fp16.h>
#include <math.h>

#define N_NODES 100000
#define N_EDGES 3200000
#define TOT_SLOTS (N_EDGES + N_NODES)
#define SCAN_BLOCK 1024
#define SCAN_NBLK ((N_NODES + SCAN_BLOCK - 1) / SCAN_BLOCK)   // 98
#define SRC_MASK 0x1FFFF
#define Q15_INV (1.0f / 32767.0f)

// Device-global scratch (zero-init at load; g_deg/g_acc re-zeroed each run).
__device__ float4 g_x0[(size_t)N_NODES * 2];   // level-0 features fp32
__device__ float4 g_x1[(size_t)N_NODES * 2];   // level-1 features fp32 (for epi2)
__device__ uint4  g_yh[(size_t)N_NODES];       // conv1 operand fp16: dinv*(bv1+wv1*x0) 16B
__device__ uint4  g_r2h[(size_t)N_NODES * 2];  // conv2 operand fp16 {x1,d01} 32B
__device__ uint4  g_r3h[(size_t)N_NODES * 4];  // conv3 operand fp16 {x2,d02,d12,pad} 64B
__device__ float4 g_acc[(size_t)N_NODES * 2];  // per-layer accumulator
__device__ float4 g_q[(size_t)N_NODES * 2];    // per-node qk[8] (0.5*q*wk)
__device__ float  g_dinv[N_NODES];
__device__ int    g_deg[N_NODES];
__device__ int    g_cursor[N_NODES];
__device__ int2   g_csr[TOT_SLOTS];   // {src | q15(dinv[src])<<17, dst}
__device__ int    g_bsum[SCAN_NBLK];

// ---- fp16 pack/unpack (8 floats <-> uint4 of 8 halves) ----
__device__ __forceinline__ void h8_to_f(const uint4& u, float o[8]) {
    const __half2* h = (const __half2*)&u;
    #pragma unroll
    for (int i = 0; i < 4; i++) {
        float2 f = __half22float2(h[i]);
        o[2 * i] = f.x; o[2 * i + 1] = f.y;
    }
}
__device__ __forceinline__ uint4 f_to_h8(const float o[8]) {
    uint4 u;
    __half2* h = (__half2*)&u;
    #pragma unroll
    for (int i = 0; i < 4; i++)
        h[i] = __float22half2_rn(make_float2(o[2 * i], o[2 * i + 1]));
    return u;
}

// ---- packed f32x2 helpers ----
__device__ __forceinline__ unsigned long long ADDX2(unsigned long long a, unsigned long long b) {
    unsigned long long r;
    asm("add.rn.f32x2 %0, %1, %2;" : "=l"(r) : "l"(a), "l"(b));
    return r;
}
__device__ __forceinline__ unsigned long long PACK2(float lo, float hi) {
    unsigned long long r;
    asm("mov.b64 %0, {%1, %2};" : "=l"(r) : "f"(lo), "f"(hi));
    return r;
}
__device__ __forceinline__ void UNPACK2(unsigned long long v, float& lo, float& hi) {
    asm("mov.b64 {%0, %1}, %2;" : "=f"(lo), "=f"(hi) : "l"(v));
}
__device__ __forceinline__ void flush8(int dst, const float r[8]) {
    float* a = (float*)g_acc + (size_t)dst * 8;
    asm volatile("red.global.add.v4.f32 [%0], {%1,%2,%3,%4};"
                 :: "l"(a), "f"(r[0]), "f"(r[1]), "f"(r[2]), "f"(r[3]) : "memory");
    asm volatile("red.global.add.v4.f32 [%0], {%1,%2,%3,%4};"
                 :: "l"(a + 4), "f"(r[4]), "f"(r[5]), "f"(r[6]), "f"(r[7]) : "memory");
}
__device__ __forceinline__ unsigned lanemask_le() {
    unsigned m; asm("mov.u32 %0, %%lanemask_le;" : "=r"(m)); return m;
}

// (head,tail)-run segmented reduction across lanes keyed by dst (-1 invalid).
// A = lane's head run (partial sums flushed atomically are fine), B = tail run.
__device__ __forceinline__ void pair_reduce_flush(
    const float mA[8], const float mB[8], int dstA, int dstB, int lane)
{
    int prevB = __shfl_up_sync(0xffffffffu, dstB, 1);
    bool start = (lane == 0) || (dstA != dstB) || (prevB != dstA);
    unsigned startmask = __ballot_sync(0xffffffffu, start);
    int segid = __popc(startmask & lanemask_le());

    if (dstA != dstB && dstA >= 0) flush8(dstA, mA);   // head run closes mid-lane

    unsigned long long p[4];
    bool same = (dstA == dstB);
    #pragma unroll
    for (int i = 0; i < 4; i++) {
        unsigned long long b_ = PACK2(mB[2 * i], mB[2 * i + 1]);
        p[i] = same ? ADDX2(PACK2(mA[2 * i], mA[2 * i + 1]), b_) : b_;
    }
    #pragma unroll
    for (int off = 1; off < 32; off <<= 1) {
        int s2 = __shfl_up_sync(0xffffffffu, segid, off);
        bool take = (lane >= off) && (s2 == segid);
        #pragma unroll
        for (int i = 0; i < 4; i++) {
            unsigned long long t = __shfl_up_sync(0xffffffffu, p[i], off);
            if (take) p[i] = ADDX2(p[i], t);
        }
    }
    bool end = (lane == 31) || ((startmask >> (lane + 1)) & 1u);
    if (end && dstB >= 0) {
        float r[8];
        UNPACK2(p[0], r[0], r[1]); UNPACK2(p[1], r[2], r[3]);
        UNPACK2(p[2], r[4], r[5]); UNPACK2(p[3], r[6], r[7]);
        flush8(dstB, r);
    }
}

// local run-combine over 4 sequential messages, then cross-lane reduce
struct RunAcc {
    int dA, dB;
    float sA[8], sB[8];
    __device__ __forceinline__ void init() {
        dA = -1; dB = -1;
        #pragma unroll
        for (int c = 0; c < 8; c++) { sA[c] = 0.f; sB[c] = 0.f; }
    }
    __device__ __forceinline__ void add(int d, const float m[8]) {
        if (d == dB) {
            #pragma unroll
            for (int c = 0; c < 8; c++) sB[c] += m[c];
        } else {
            if (dB >= 0) {
                if (dA < 0) {
                    dA = dB;
                    #pragma unroll
                    for (int c = 0; c < 8; c++) sA[c] = sB[c];
                } else {
                    flush8(dB, sB);          // interior run: direct atomic
                }
            }
            dB = d;
            #pragma unroll
            for (int c = 0; c < 8; c++) sB[c] = m[c];
        }
    }
    __device__ __forceinline__ void finish(int lane) {
        if (dA < 0) {
            dA = dB;                          // single-run lane: A zero, same key
            #pragma unroll
            for (int c = 0; c < 8; c++) sA[c] = 0.f;
        }
        pair_reduce_flush(sA, sB, dA, dB, lane);
    }
};

// load 4 consecutive CSR entries for this lane ({0,-1} past the end)
__device__ __forceinline__ void load4(int idx0, int2 e[4]) {
    #pragma unroll
    for (int k = 0; k < 4; k++) e[k] = make_int2(0, -1);
    if (idx0 + 3 < TOT_SLOTS) {
        int4 v0 = __ldg((const int4*)(g_csr + idx0));
        int4 v1 = __ldg((const int4*)(g_csr + idx0 + 2));
        e[0] = make_int2(v0.x, v0.y); e[1] = make_int2(v0.z, v0.w);
        e[2] = make_int2(v1.x, v1.y); e[3] = make_int2(v1.z, v1.w);
    } else {
        #pragma unroll
        for (int k = 0; k < 4; k++)
            if (idx0 + k < TOT_SLOTS) e[k] = __ldg(&g_csr[idx0 + k]);
    }
}

// ---------------- CSR build ----------------

__global__ void count_kernel(const int4* __restrict__ dst4) {
    int e = blockIdx.x * blockDim.x + threadIdx.x;
    if (e < N_EDGES / 4) {
        int4 d = __ldg(&dst4[e]);
        atomicAdd(&g_deg[d.x], 1);
        atomicAdd(&g_deg[d.y], 1);
        atomicAdd(&g_deg[d.z], 1);
        atomicAdd(&g_deg[d.w], 1);
    }
}

// warp-shuffle block scan
__global__ void scan1_kernel() {
    __shared__ int wsum[32];
    int t = threadIdx.x, lane = t & 31, wid = t >> 5;
    int i = blockIdx.x * SCAN_BLOCK + t;
    int v = 0;
    if (i < N_NODES) {
        v = g_deg[i] + 1;                 // +1 self loop
        g_dinv[i] = rsqrtf((float)v);
        g_deg[i] = 0;                     // restore entry invariant
    }
    int x = v;
    #pragma unroll
    for (int o = 1; o < 32; o <<= 1) {
        int y = __shfl_up_sync(0xffffffffu, x, o);
        if (lane >= o) x += y;
    }
    if (lane == 31) wsum[wid] = x;
    __syncthreads();
    if (wid == 0) {
        int s = wsum[lane];
        #pragma unroll
        for (int o = 1; o < 32; o <<= 1) {
            int y = __shfl_up_sync(0xffffffffu, s, o);
            if (lane >= o) s += y;
        }
        wsum[lane] = s;
    }
    __syncthreads();
    int incl = x + (wid ? wsum[wid - 1] : 0);
    if (i < N_NODES) g_cursor[i] = incl - v;       // exclusive (block-local)
    if (t == SCAN_BLOCK - 1) g_bsum[blockIdx.x] = incl;
}

// block-prefix fixup + self-loop CSR + cursor + MLP + y(fp16, dinv-scaled)
__global__ void scan3_fill_mlp_kernel(const float* __restrict__ x,
                                      const int* __restrict__ node_index,
                                      const float* __restrict__ emb,
                                      const float* __restrict__ W1,
                                      const float* __restrict__ b1,
                                      const float* __restrict__ Wv1,
                                      const float* __restrict__ Bv1) {
    __shared__ float sW[24 * 8 + 8];
    __shared__ int sPre;
    int t = threadIdx.x;
    if (t < 192) sW[t] = W1[t];
    else if (t < 200) sW[t] = b1[t - 192];
    if (t < 32) {                       // warp 0: prefix of bsum[0..bid)
        int s = 0;
        for (int j = t; j < SCAN_NBLK; j += 32)
            if (j < (int)blockIdx.x) s += g_bsum[j];
        #pragma unroll
        for (int o = 16; o; o >>= 1) s += __shfl_xor_sync(0xffffffffu, s, o);
        if (t == 0) sPre = s;
    }
    __syncthreads();

    int i = blockIdx.x * SCAN_BLOCK + t;
    if (i >= N_NODES) return;

    int off = g_cursor[i] + sPre;
    float di = g_dinv[i];
    int q = __float2int_rn(di * 32767.0f);
    g_csr[off] = make_int2(i | (q << 17), i);      // self loop
    g_cursor[i] = off + 1;

    float in[24];
    int idx = node_index[i];
    #pragma unroll
    for (int j = 0; j < 8; j++) in[j] = emb[(size_t)idx * 8 + j];
    #pragma unroll
    for (int j = 0; j < 16; j++) in[8 + j] = x[(size_t)i * 16 + j];
    float o[8], y[8];
    #pragma unroll
    for (int c = 0; c < 8; c++) {
        float s = sW[192 + c];
        #pragma unroll
        for (int j = 0; j < 24; j++) s = fmaf(in[j], sW[j * 8 + c], s);
        o[c] = fmaxf(s, 0.0f);
        y[c] = di * fmaf(__ldg(Wv1 + c), o[c], __ldg(Bv1 + c));
    }
    g_x0[(size_t)i * 2]     = make_float4(o[0], o[1], o[2], o[3]);
    g_x0[(size_t)i * 2 + 1] = make_float4(o[4], o[5], o[6], o[7]);
    g_yh[i] = f_to_h8(y);
}

__global__ void fill_edges_kernel(const int* __restrict__ src, const int* __restrict__ dst) {
    int e = blockIdx.x * blockDim.x + threadIdx.x;
    if (e < N_EDGES) {
        int s = src[e];
        int d = dst[e];
        int q = __float2int_rn(g_dinv[s] * 32767.0f);
        int p = atomicAdd(&g_cursor[d], 1);
        g_csr[p] = make_int2(s | (q << 17), d);
    }
}

// ---------------- conv1: quad-slot SpMV of fp16 y ---------------------------

__global__ void __launch_bounds__(256) econv1_kernel() {
    int warp = threadIdx.x >> 5, lane = threadIdx.x & 31;
    int base = (blockIdx.x * 8 + warp) * 128;
    if (base >= TOT_SLOTS) return;
    int idx0 = base + 4 * lane;

    int2 e[4];
    load4(idx0, e);

    RunAcc acc; acc.init();
    #pragma unroll
    for (int k = 0; k < 4; k++) {
        if (e[k].y < 0) continue;
        float m[8];
        h8_to_f(__ldg(&g_yh[e[k].x & SRC_MASK]), m);
        acc.add(e[k].y, m);
    }
    acc.finish(lane);
}

// ---------------- conv2: quad-slot, fp16 records (32B/edge) -----------------

__device__ __forceinline__ void conv2_msg(const uint4& c0, const uint4& c1,
                                          const float4& q0, const float4& q1,
                                          float w, const float* Wv, const float* Bv, float m[8]) {
    float x1[8], d01[8];
    h8_to_f(c0, x1);
    h8_to_f(c1, d01);
    float qk[8] = {q0.x, q0.y, q0.z, q0.w, q1.x, q1.y, q1.z, q1.w};
    float a[2];
    #pragma unroll
    for (int h = 0; h < 2; h++) {
        float s_ = 0.0f;
        #pragma unroll
        for (int d = 0; d < 4; d++) s_ = fmaf(qk[h * 4 + d], d01[h * 4 + d], s_);
        a[h] = 1.0f / (1.0f + __expf(-s_));
    }
    #pragma unroll
    for (int c = 0; c < 8; c++) {
        float t = fmaf(a[c >> 2], d01[c], x1[c]);
        m[c] = w * fmaf(__ldg(Wv + c), t, __ldg(Bv + c));
    }
}

__global__ void __launch_bounds__(256) econv2_kernel(
    const float* __restrict__ Wv, const float* __restrict__ Bv)
{
    int warp = threadIdx.x >> 5, lane = threadIdx.x & 31;
    int base = (blockIdx.x * 8 + warp) * 128;
    if (base >= TOT_SLOTS) return;
    int idx0 = base + 4 * lane;

    int2 e[4];
    load4(idx0, e);

    RunAcc acc; acc.init();
    #pragma unroll
    for (int k = 0; k < 4; k++) {
        if (e[k].y < 0) continue;
        int s = e[k].x & SRC_MASK;
        uint4 c0 = __ldg(g_r2h + (size_t)s * 2);
        uint4 c1 = __ldg(g_r2h + (size_t)s * 2 + 1);   // same 32B sector: L1 hit
        float4 q0 = __ldg(g_q + (size_t)e[k].y * 2);
        float4 q1 = __ldg(g_q + (size_t)e[k].y * 2 + 1);
        float w = (float)((unsigned)e[k].x >> 17) * Q15_INV;
        float m[8];
        conv2_msg(c0, c1, q0, q1, w, Wv, Bv, m);
        acc.add(e[k].y, m);
    }
    acc.finish(lane);
}

// ---------------- conv3: quad-slot, fp16 records (48B in 64B slot) ----------

__device__ __forceinline__ void conv3_msg(const uint4& c0, const uint4& c1, const uint4& c2,
                                          const float4& q0, const float4& q1,
                                          float w, const float* Wv, const float* Bv, float m[8]) {
    float x2[8], d02[8], d12[8];
    h8_to_f(c0, x2);
    h8_to_f(c1, d02);
    h8_to_f(c2, d12);
    float qk[8] = {q0.x, q0.y, q0.z, q0.w, q1.x, q1.y, q1.z, q1.w};
    float a0[2], a1[2];
    #pragma unroll
    for (int h = 0; h < 2; h++) {
        float t0 = 0.0f, t1 = 0.0f;
        #pragma unroll
        for (int d = 0; d < 4; d++) {
            t0 = fmaf(qk[h * 4 + d], d02[h * 4 + d], t0);
            t1 = fmaf(qk[h * 4 + d], d12[h * 4 + d], t1);
        }
        float mx = fmaxf(fmaxf(t0, t1), 0.0f);
        float e0 = __expf(t0 - mx), e1 = __expf(t1 - mx), e2 = __expf(-mx);
        float inv = 1.0f / (e0 + e1 + e2);
        a0[h] = e0 * inv; a1[h] = e1 * inv;
    }
    #pragma unroll
    for (int c = 0; c < 8; c++) {
        int h = c >> 2;
        float t = fmaf(a0[h], d02[c], fmaf(a1[h], d12[c], x2[c]));
        m[c] = w * fmaf(__ldg(Wv + c), t, __ldg(Bv + c));
    }
}

__global__ void __launch_bounds__(256) econv3_kernel(
    const float* __restrict__ Wv, const float* __restrict__ Bv)
{
    int warp = threadIdx.x >> 5, lane = threadIdx.x & 31;
    int base = (blockIdx.x * 8 + warp) * 128;
    if (base >= TOT_SLOTS) return;
    int idx0 = base + 4 * lane;

    int2 e[4];
    load4(idx0, e);

    RunAcc acc; acc.init();
    #pragma unroll
    for (int k = 0; k < 4; k++) {
        if (e[k].y < 0) continue;
        int s = e[k].x & SRC_MASK;
        uint4 c0 = __ldg(g_r3h + (size_t)s * 4);
        uint4 c1 = __ldg(g_r3h + (size_t)s * 4 + 1);   // same 128B line: L1 hit
        uint4 c2 = __ldg(g_r3h + (size_t)s * 4 + 2);
        float4 q0 = __ldg(g_q + (size_t)e[k].y * 2);
        float4 q1 = __ldg(g_q + (size_t)e[k].y * 2 + 1);
        float w = (float)((unsigned)e[k].x >> 17) * Q15_INV;
        float m[8];
        conv3_msg(c0, c1, c2, q0, q1, w, Wv, Bv, m);
        acc.add(e[k].y, m);
    }
    acc.finish(lane);
}

// ---------------- epilogues (all scale by dinv[n]) ----------------

__global__ void epi1_kernel(const float* __restrict__ Wq2, const float* __restrict__ Bq2,
                            const float* __restrict__ Wk2) {
    int n = blockIdx.x * blockDim.x + threadIdx.x;
    if (n >= N_NODES) return;
    float4 a = g_acc[(size_t)n * 2];
    float4 b = g_acc[(size_t)n * 2 + 1];
    float4 z4 = make_float4(0.f, 0.f, 0.f, 0.f);
    g_acc[(size_t)n * 2] = z4;
    g_acc[(size_t)n * 2 + 1] = z4;
    float di = g_dinv[n];
    float x1[8] = {fmaxf(di * a.x, 0.f), fmaxf(di * a.y, 0.f), fmaxf(di * a.z, 0.f), fmaxf(di * a.w, 0.f),
                   fmaxf(di * b.x, 0.f), fmaxf(di * b.y, 0.f), fmaxf(di * b.z, 0.f), fmaxf(di * b.w, 0.f)};
    float4 xa = g_x0[(size_t)n * 2];
    float4 xb = g_x0[(size_t)n * 2 + 1];
    float x0[8] = {xa.x, xa.y, xa.z, xa.w, xb.x, xb.y, xb.z, xb.w};
    float d01[8];
    #pragma unroll
    for (int c = 0; c < 8; c++) d01[c] = x0[c] - x1[c];
    g_x1[(size_t)n * 2]     = make_float4(x1[0], x1[1], x1[2], x1[3]);
    g_x1[(size_t)n * 2 + 1] = make_float4(x1[4], x1[5], x1[6], x1[7]);
    g_r2h[(size_t)n * 2]     = f_to_h8(x1);
    g_r2h[(size_t)n * 2 + 1] = f_to_h8(d01);
    float qk[8];
    #pragma unroll
    for (int c = 0; c < 8; c++) {
        float q = fmaf(x1[c], __ldg(Wq2 + c), __ldg(Bq2 + c));
        qk[c] = 0.5f * q * __ldg(Wk2 + c);
    }
    g_q[(size_t)n * 2]     = make_float4(qk[0], qk[1], qk[2], qk[3]);
    g_q[(size_t)n * 2 + 1] = make_float4(qk[4], qk[5], qk[6], qk[7]);
}

__global__ void epi2_kernel(const float* __restrict__ Wq3, const float* __restrict__ Bq3,
                            const float* __restrict__ Wk3) {
    int n = blockIdx.x * blockDim.x + threadIdx.x;
    if (n >= N_NODES) return;
    float4 a = g_acc[(size_t)n * 2];
    float4 b = g_acc[(size_t)n * 2 + 1];
    float4 z4 = make_float4(0.f, 0.f, 0.f, 0.f);
    g_acc[(size_t)n * 2] = z4;
    g_acc[(size_t)n * 2 + 1] = z4;
    float di = g_dinv[n];
    float x2[8] = {fmaxf(di * a.x, 0.f), fmaxf(di * a.y, 0.f), fmaxf(di * a.z, 0.f), fmaxf(di * a.w, 0.f),
                   fmaxf(di * b.x, 0.f), fmaxf(di * b.y, 0.f), fmaxf(di * b.z, 0.f), fmaxf(di * b.w, 0.f)};
    float4 xa = g_x0[(size_t)n * 2];
    float4 xb = g_x0[(size_t)n * 2 + 1];
    float4 ya = g_x1[(size_t)n * 2];
    float4 yb = g_x1[(size_t)n * 2 + 1];
    float x0[8] = {xa.x, xa.y, xa.z, xa.w, xb.x, xb.y, xb.z, xb.w};
    float x1[8] = {ya.x, ya.y, ya.z, ya.w, yb.x, yb.y, yb.z, yb.w};
    float d02[8], d12[8];
    #pragma unroll
    for (int c = 0; c < 8; c++) { d02[c] = x0[c] - x2[c]; d12[c] = x1[c] - x2[c]; }
    g_r3h[(size_t)n * 4]     = f_to_h8(x2);
    g_r3h[(size_t)n * 4 + 1] = f_to_h8(d02);
    g_r3h[(size_t)n * 4 + 2] = f_to_h8(d12);
    float qk[8];
    #pragma unroll
    for (int c = 0; c < 8; c++) {
        float q = fmaf(x2[c], __ldg(Wq3 + c), __ldg(Bq3 + c));
        qk[c] = 0.5f * q * __ldg(Wk3 + c);
    }
    g_q[(size_t)n * 2]     = make_float4(qk[0], qk[1], qk[2], qk[3]);
    g_q[(size_t)n * 2 + 1] = make_float4(qk[4], qk[5], qk[6], qk[7]);
}

__global__ void epi3_kernel(const float* __restrict__ W2, const float* __restrict__ b2,
                            float* __restrict__ out) {
    int n = blockIdx.x * blockDim.x + threadIdx.x;
    if (n >= N_NODES) return;
    float4 a = g_acc[(size_t)n * 2];
    float4 b = g_acc[(size_t)n * 2 + 1];
    float4 z4 = make_float4(0.f, 0.f, 0.f, 0.f);
    g_acc[(size_t)n * 2] = z4;
    g_acc[(size_t)n * 2 + 1] = z4;
    float di = g_dinv[n];
    float xl[8] = {fmaxf(di * a.x, 0.f), fmaxf(di * a.y, 0.f), fmaxf(di * a.z, 0.f), fmaxf(di * a.w, 0.f),
                   fmaxf(di * b.x, 0.f), fmaxf(di * b.y, 0.f), fmaxf(di * b.z, 0.f), fmaxf(di * b.w, 0.f)};
    float z0 = __ldg(b2 + 0), z1 = __ldg(b2 + 1);
    #pragma unroll
    for (int c = 0; c < 8; c++) {
        z0 = fmaf(xl[c], __ldg(W2 + c * 2 + 0), z0);
        z1 = fmaf(xl[c], __ldg(W2 + c * 2 + 1), z1);
    }
    float mx = fmaxf(z0, z1);
    float lse = mx + __logf(__expf(z0 - mx) + __expf(z1 - mx));
    out[(size_t)n * 2 + 0] = z0 - lse;
    out[(size_t)n * 2 + 1] = z1 - lse;
}

// ---------------- launch ----------------

extern "C" void kernel_launch(void* const* d_in, const int* in_sizes, int n_in,
                              void* d_out, int out_size) {
    const float* x    = (const float*)d_in[0];
    const int*   nidx = (const int*)  d_in[1];
    const int*   eidx = (const int*)  d_in[3];   // [2, E]
    const float* emb  = (const float*)d_in[5];
    const float* W1   = (const float*)d_in[6];
    const float* b1   = (const float*)d_in[7];
    const float* Wq   = (const float*)d_in[8];
    const float* bq   = (const float*)d_in[9];
    const float* Wk   = (const float*)d_in[10];
    const float* Wv   = (const float*)d_in[12];
    const float* bv   = (const float*)d_in[13];
    const float* W2   = (const float*)d_in[14];
    const float* b2   = (const float*)d_in[15];
    float* out = (float*)d_out;

    const int* src = eidx;
    const int* dst = eidx + N_EDGES;

    int nb_n  = (N_NODES + 255) / 256;
    int nb_e  = (N_EDGES + 255) / 256;
    int nb_e4 = (N_EDGES / 4 + 255) / 256;
    int nb_q  = (TOT_SLOTS + 1023) / 1024;        // 8 warps x 128 slots

    count_kernel<<<nb_e4, 256>>>((const int4*)dst);
    scan1_kernel<<<SCAN_NBLK, SCAN_BLOCK>>>();
    scan3_fill_mlp_kernel<<<SCAN_NBLK, SCAN_BLOCK>>>(x, nidx, emb, W1, b1, Wv + 0, bv + 0);
    fill_edges_kernel<<<nb_e, 256>>>(src, dst);

    econv1_kernel<<<nb_q, 256>>>();
    epi1_kernel<<<nb_n, 256>>>(Wq + 8, bq + 8, Wk + 8);
    econv2_kernel<<<nb_q, 256>>>(Wv + 8, bv + 8);
    epi2_kernel<<<nb_n, 256>>>(Wq + 16, bq + 16, Wk + 16);
    econv3_kernel<<<nb_q, 256>>>(Wv + 16, bv + 16);
    epi3_kernel<<<nb_n, 256>>>(W2, b2, out);
}